// round 12
// baseline (speedup 1.0000x reference)
#include <cuda_runtime.h>
#include <cuda_fp16.h>
#include <math.h>
#include <stdint.h>

#define NBATCH 16
#define SEQ    2048
#define EMB    256
#define NROWS  (NBATCH*SEQ)
#define FFND   512
#define ROWS   128
#define XSTR   264            // row stride in halves (528 B: conflict-free ldmatrix)

__device__ float  g_freq[128];
__device__ __half g_wt_attn[2*256*256];   // [f][e]
__device__ __half g_wt_ffn[2*256*FFND];   // [e][f]
__device__ float  g_pool[256*EMB];

// ---------------- asm helpers ----------------
__device__ __forceinline__ void mma16(float* d, const uint32_t* a, const uint32_t* b){
    asm volatile("mma.sync.aligned.m16n8k16.row.col.f32.f16.f16.f32 "
        "{%0,%1,%2,%3}, {%4,%5,%6,%7}, {%8,%9}, {%0,%1,%2,%3};"
        : "+f"(d[0]),"+f"(d[1]),"+f"(d[2]),"+f"(d[3])
        : "r"(a[0]),"r"(a[1]),"r"(a[2]),"r"(a[3]),"r"(b[0]),"r"(b[1]));
}
__device__ __forceinline__ void ldsm4(uint32_t& r0, uint32_t& r1, uint32_t& r2, uint32_t& r3,
                                      uint32_t addr){
    asm volatile("ldmatrix.sync.aligned.m8n8.x4.shared.b16 {%0,%1,%2,%3}, [%4];"
        : "=r"(r0),"=r"(r1),"=r"(r2),"=r"(r3) : "r"(addr));
}
__device__ __forceinline__ uint32_t smem_u32(const void* p){
    uint32_t a;
    asm("{ .reg .u64 t; cvta.to.shared.u64 t, %1; cvt.u32.u64 %0, t; }" : "=r"(a) : "l"(p));
    return a;
}
__device__ __forceinline__ void cpasync16(uint32_t dst, const void* src){
    asm volatile("cp.async.cg.shared.global [%0], [%1], 16;" :: "r"(dst), "l"(src));
}
__device__ __forceinline__ void cpcommit(){ asm volatile("cp.async.commit_group;" ::: "memory"); }
__device__ __forceinline__ void cpwait0(){ asm volatile("cp.async.wait_group 0;" ::: "memory"); }

// ---------------- setup kernels ----------------
__global__ void k_freq(){
    int i = threadIdx.x;
    if (i < 128) g_freq[i] = (float)exp(-(double)(2*i) * (log(10000.0) / 256.0));
}
__global__ void k_tr_attn(const float* __restrict__ W){
    int l = blockIdx.y, idx = blockIdx.x*256 + threadIdx.x;
    int e = idx & 255, f = idx >> 8;
    g_wt_attn[l*65536 + f*256 + e] = __float2half_rn(W[l*65536 + e*256 + f]);
}
__global__ void k_tr_ffn(const float* __restrict__ W2){
    int l = blockIdx.y, idx = blockIdx.x*256 + threadIdx.x;
    int f = idx & 511, e = idx >> 9;
    g_wt_ffn[l*131072 + e*512 + f] = __float2half_rn(W2[l*131072 + f*256 + e]);
}

// ---------------- smem layout (bytes) ----------------
// Xs @0       128 x 264 half = 67584
// As @67584   128 x 264 half = 67584  (A or h K-half, stride 264)
// Bs @135168  2 x (64 x 264 half = 33792) = 67584
// qs @202752  128 x 9 f32 = 4608      -> 207360 total, 1 CTA/SM
// S/P alias As
#define OFF_AS  67584
#define OFF_BS  135168
#define OFF_QS  202752
#define SM_TOT  207360

// ---------------- pure mma loop: one 64-col chunk, K=256, 64 mma ----------------
__device__ __forceinline__ void mma_all(uint32_t as_u32, uint32_t bs_u32,
                                        int wm, int wn, int lane,
                                        float acc[2][2][4]){
    int g = lane >> 3, i = lane & 7;
    uint32_t abase = as_u32 + (uint32_t)((wm*32 + (g&1)*8 + i)*528 + (g>>1)*16);
    uint32_t bbase = bs_u32 + (uint32_t)((wn*16 + (g>>1)*8 + i)*528 + (g&1)*16);
    #pragma unroll
    for (int ks = 0; ks < 16; ks++){
        uint32_t a0[4], a1[4], b[4];
        ldsm4(a0[0],a0[1],a0[2],a0[3], abase + ks*32);
        ldsm4(a1[0],a1[1],a1[2],a1[3], abase + 16*528 + ks*32);
        ldsm4(b[0],b[1],b[2],b[3], bbase + ks*32);
        mma16(acc[0][0], a0, &b[0]);
        mma16(acc[0][1], a0, &b[2]);
        mma16(acc[1][0], a1, &b[0]);
        mma16(acc[1][1], a1, &b[2]);
    }
}

// ---------------- staging (512 threads) ----------------
__device__ __forceinline__ void stageB_async(uint32_t bs_u32, const __half* __restrict__ Wt,
                                             int rowlen, int nc, int koff, int tid){
    #pragma unroll
    for (int i = 0; i < 4; i++){
        int idx = tid + 512*i;
        int seg = idx & 31, n = idx >> 5;
        cpasync16(bs_u32 + (uint32_t)(n*528 + seg*16),
                  Wt + (nc*64 + n)*rowlen + koff + seg*8);
    }
}
__device__ __forceinline__ void stageA_attn(__half* __restrict__ As,
        const __half* __restrict__ Xs, const float* __restrict__ theta, int tid){
    #pragma unroll
    for (int i = 0; i < 16; i++){
        int idx = tid + 512*i;
        int kk4 = (idx & 63)*4, r = idx >> 6;
        uint2 xr = *(const uint2*)&Xs[r*XSTR + kk4];
        float2 x01 = __half22float2(*(const __half2*)&xr.x);
        float2 x23 = __half22float2(*(const __half2*)&xr.y);
        __half2 h01 = __floats2half2_rn(__cosf(x01.x + __ldg(&theta[(kk4+0)&63])),
                                        __cosf(x01.y + __ldg(&theta[(kk4+1)&63])));
        __half2 h23 = __floats2half2_rn(__cosf(x23.x + __ldg(&theta[(kk4+2)&63])),
                                        __cosf(x23.y + __ldg(&theta[(kk4+3)&63])));
        uint2 pk; pk.x = *(const uint32_t*)&h01; pk.y = *(const uint32_t*)&h23;
        *(uint2*)&As[r*XSTR + kk4] = pk;
    }
}
__device__ __forceinline__ void stageA_ffn(__half* __restrict__ As,
        const float* __restrict__ qs, const float* __restrict__ W1,
        const float* __restrict__ b1, int kh, int tid){
    int fcol = tid & 255, rg = tid >> 8;
    float wcol[8];
    #pragma unroll
    for (int n = 0; n < 8; n++) wcol[n] = __ldg(&W1[n*FFND + kh*256 + fcol]);
    float bf = __ldg(&b1[kh*256 + fcol]);
    #pragma unroll 4
    for (int rr = 0; rr < 64; rr++){
        int r = rg*64 + rr;
        float a = bf;
        #pragma unroll
        for (int n = 0; n < 8; n++) a += qs[r*9 + n] * wcol[n];
        As[r*XSTR + fcol] = __float2half_rn(fmaxf(a, 0.f));
    }
}

// ---------------- register epilogue: Xs = LN(Xs + D + bias) ----------------
__device__ __forceinline__ void epilogue(__half* __restrict__ Xs, float* __restrict__ S,
        float acc4[4][2][2][4], int wm, int wn, int gid, int tig,
        const float* __restrict__ bias, const float* __restrict__ lng,
        const float* __restrict__ lnb){
    #pragma unroll
    for (int nc = 0; nc < 4; nc++)
        #pragma unroll
        for (int tm = 0; tm < 2; tm++){
            int rl = wm*32 + tm*16 + gid;
            #pragma unroll
            for (int tn = 0; tn < 2; tn++){
                int col = nc*64 + wn*16 + tn*8 + 2*tig;
                float bx = __ldg(&bias[col]), by = __ldg(&bias[col+1]);
                float2 x0 = __half22float2(*(const __half2*)&Xs[rl*XSTR + col]);
                float2 x1 = __half22float2(*(const __half2*)&Xs[(rl+8)*XSTR + col]);
                acc4[nc][tm][tn][0] += bx + x0.x; acc4[nc][tm][tn][1] += by + x0.y;
                acc4[nc][tm][tn][2] += bx + x1.x; acc4[nc][tm][tn][3] += by + x1.y;
            }
        }
    float s[2][2], q[2][2];
    #pragma unroll
    for (int tm = 0; tm < 2; tm++){
        s[tm][0] = s[tm][1] = q[tm][0] = q[tm][1] = 0.f;
        #pragma unroll
        for (int nc = 0; nc < 4; nc++)
            #pragma unroll
            for (int tn = 0; tn < 2; tn++){
                s[tm][0] += acc4[nc][tm][tn][0] + acc4[nc][tm][tn][1];
                q[tm][0] += acc4[nc][tm][tn][0]*acc4[nc][tm][tn][0] + acc4[nc][tm][tn][1]*acc4[nc][tm][tn][1];
                s[tm][1] += acc4[nc][tm][tn][2] + acc4[nc][tm][tn][3];
                q[tm][1] += acc4[nc][tm][tn][2]*acc4[nc][tm][tn][2] + acc4[nc][tm][tn][3]*acc4[nc][tm][tn][3];
            }
    }
    #pragma unroll
    for (int off = 1; off <= 2; off <<= 1)
        #pragma unroll
        for (int tm = 0; tm < 2; tm++)
            #pragma unroll
            for (int h = 0; h < 2; h++){
                s[tm][h] += __shfl_xor_sync(0xffffffffu, s[tm][h], off);
                q[tm][h] += __shfl_xor_sync(0xffffffffu, q[tm][h], off);
            }
    if (tig == 0){
        #pragma unroll
        for (int tm = 0; tm < 2; tm++){
            int rl = wm*32 + tm*16 + gid;
            S[rl*8 + wn*2]        = s[tm][0];
            S[rl*8 + wn*2 + 1]    = q[tm][0];
            S[(rl+8)*8 + wn*2]    = s[tm][1];
            S[(rl+8)*8 + wn*2 +1] = q[tm][1];
        }
    }
    __syncthreads();
    #pragma unroll
    for (int tm = 0; tm < 2; tm++){
        int rl = wm*32 + tm*16 + gid;
        #pragma unroll
        for (int h = 0; h < 2; h++){
            int r = rl + 8*h;
            float Ss = S[r*8+0] + S[r*8+2] + S[r*8+4] + S[r*8+6];
            float Qq = S[r*8+1] + S[r*8+3] + S[r*8+5] + S[r*8+7];
            float m  = Ss * (1.f/256.f);
            float var = fmaxf(Qq * (1.f/256.f) - m*m, 0.f);
            float rs = rsqrtf(var + 1e-5f);
            #pragma unroll
            for (int nc = 0; nc < 4; nc++)
                #pragma unroll
                for (int tn = 0; tn < 2; tn++){
                    int col = nc*64 + wn*16 + tn*8 + 2*tig;
                    float z0 = acc4[nc][tm][tn][2*h], z1 = acc4[nc][tm][tn][2*h+1];
                    *(__half2*)&Xs[r*XSTR + col] =
                        __floats2half2_rn((z0-m)*rs*__ldg(&lng[col]) + __ldg(&lnb[col]),
                                          (z1-m)*rs*__ldg(&lng[col+1]) + __ldg(&lnb[col+1]));
                }
        }
    }
}

// ---------------- fused kernel ----------------
__global__ __launch_bounds__(512, 1) void k_fused(
    const int* __restrict__ tokens, const float* __restrict__ embed,
    const float* __restrict__ attn_theta, const float* __restrict__ combine_b,
    const float* __restrict__ ffn_theta,  const float* __restrict__ lin1_w,
    const float* __restrict__ lin1_b,     const float* __restrict__ lin2_b,
    const float* __restrict__ ln1g, const float* __restrict__ ln1b,
    const float* __restrict__ ln2g, const float* __restrict__ ln2b)
{
    extern __shared__ char sm[];
    __half* Xs  = (__half*)sm;
    __half* As  = (__half*)(sm + OFF_AS);
    __half* Bs  = (__half*)(sm + OFF_BS);
    float*  qs  = (float*)(sm + OFF_QS);
    float*  S   = (float*)(sm + OFF_AS);   // alias (post-GEMM only)
    uint32_t as_u32 = smem_u32(As);
    uint32_t bs_u32 = smem_u32(Bs);

    int tid = threadIdx.x, lane = tid & 31, wid = tid >> 5;
    int gid = lane >> 2, tig = lane & 3;
    int wm = wid & 3, wn = wid >> 2;   // 4m x 4n, warp tile 32 x 16 per chunk
    int row0 = blockIdx.x * ROWS;

    // ---- embed + positional encoding (fp16 Xs) ----
    #pragma unroll 4
    for (int i = 0; i < 16; i++){
        int idx = tid + 512*i;
        int r = idx >> 6, c4 = (idx & 63) * 4;
        int tok = __ldg(&tokens[row0 + r]);
        float4 v = *(const float4*)&embed[tok*EMB + c4];
        float pos = (float)((row0 + r) & (SEQ-1));
        float s0,c0,s1,c1;
        sincosf(pos * g_freq[(c4>>1)+0], &s0, &c0);
        sincosf(pos * g_freq[(c4>>1)+1], &s1, &c1);
        __half2 lo = __floats2half2_rn(v.x + s0, v.y + c0);
        __half2 hi = __floats2half2_rn(v.z + s1, v.w + c1);
        uint2 pk; pk.x = *(const uint32_t*)&lo; pk.y = *(const uint32_t*)&hi;
        *(uint2*)&Xs[r*XSTR + c4] = pk;
    }
    __syncthreads();

    #pragma unroll 1
    for (int l = 0; l < 2; l++){
        // ================= attention =================
        {
            const float*  theta = attn_theta + l*64;
            const __half* Wt    = g_wt_attn + l*65536;
            float acc4[4][2][2][4];
            float* ap = &acc4[0][0][0][0];
            #pragma unroll
            for (int j = 0; j < 64; j++) ap[j] = 0.f;

            stageB_async(bs_u32, Wt, 256, 0, 0, tid);
            cpcommit();
            stageA_attn(As, Xs, theta, tid);
            cpwait0(); __syncthreads();

            #pragma unroll 1
            for (int nc = 0; nc < 4; nc++){
                int cur = nc & 1, nxt = cur ^ 1;
                if (nc + 1 < 4){
                    stageB_async(bs_u32 + nxt*33792u, Wt, 256, nc+1, 0, tid);
                    cpcommit();
                }
                mma_all(as_u32, bs_u32 + cur*33792u, wm, wn, lane, acc4[nc]);
                if (nc + 1 < 4) cpwait0();
                __syncthreads();
            }
            epilogue(Xs, S, acc4, wm, wn, gid, tig,
                     combine_b + l*256, ln1g + l*256, ln1b + l*256);
            __syncthreads();
        }
        // ================= ffn =================
        {
            const float*  fth = ffn_theta + l*8;
            const float*  W1  = lin1_w + l*8*FFND;
            const float*  b1  = lin1_b + l*FFND;
            const __half* Wt2 = g_wt_ffn + l*256*FFND;
            float acc4[4][2][2][4];
            float* ap = &acc4[0][0][0][0];
            #pragma unroll
            for (int j = 0; j < 64; j++) ap[j] = 0.f;

            for (int idx = tid; idx < ROWS*8; idx += 512){
                int r = idx >> 3, n = idx & 7;
                qs[r*9 + n] = __cosf(__half2float(Xs[r*XSTR + n])) * __cosf(__ldg(&fth[n]));
            }
            __syncthreads();

            #pragma unroll 1
            for (int kh = 0; kh < 2; kh++){
                stageB_async(bs_u32, Wt2, 512, 0, kh*256, tid);
                cpcommit();
                stageA_ffn(As, qs, W1, b1, kh, tid);
                cpwait0(); __syncthreads();

                #pragma unroll 1
                for (int nc = 0; nc < 4; nc++){
                    int cur = nc & 1, nxt = cur ^ 1;
                    if (nc + 1 < 4){
                        stageB_async(bs_u32 + nxt*33792u, Wt2, 512, nc+1, kh*256, tid);
                        cpcommit();
                    }
                    mma_all(as_u32, bs_u32 + cur*33792u, wm, wn, lane, acc4[nc]);
                    if (nc + 1 < 4) cpwait0();
                    __syncthreads();
                }
            }
            epilogue(Xs, S, acc4, wm, wn, gid, tig,
                     lin2_b + l*256, ln2g + l*256, ln2b + l*256);
            __syncthreads();
        }
    }

    // ---- partial pool: column sums over this CTA's 128 rows ----
    {
        int col = tid & 255, half = tid >> 8;
        float s = 0.f;
        #pragma unroll 8
        for (int r = half*64; r < half*64 + 64; r++) s += __half2float(Xs[r*XSTR + col]);
        float* P = (float*)(sm + OFF_AS);
        P[half*256 + col] = s;
        __syncthreads();
        if (tid < 256)
            g_pool[blockIdx.x*256 + tid] = P[tid] + P[256 + tid];
    }
}

// ---------------- classifier ----------------
__global__ void k_cls2(const float* __restrict__ cw, const float* __restrict__ cb,
                       float* __restrict__ out){
    int b = blockIdx.x, tid = threadIdx.x;
    float s = 0.f;
    #pragma unroll
    for (int seg = 0; seg < 16; seg++) s += g_pool[(b*16+seg)*256 + tid];
    float p = s * (1.f/(float)SEQ);
    float l0 = p * cw[tid*2 + 0];
    float l1 = p * cw[tid*2 + 1];
    #pragma unroll
    for (int off=16; off; off>>=1){
        l0 += __shfl_xor_sync(0xffffffffu, l0, off);
        l1 += __shfl_xor_sync(0xffffffffu, l1, off);
    }
    __shared__ float r0[8], r1[8];
    int warp = tid >> 5, lane = tid & 31;
    if (lane == 0){ r0[warp] = l0; r1[warp] = l1; }
    __syncthreads();
    if (tid == 0){
        float a = cb[0], c = cb[1];
        #pragma unroll
        for (int w = 0; w < 8; w++){ a += r0[w]; c += r1[w]; }
        out[b*2 + 0] = a; out[b*2 + 1] = c;
    }
}

// ---------------- launch ----------------
extern "C" void kernel_launch(void* const* d_in, const int* in_sizes, int n_in,
                              void* d_out, int out_size){
    const int*   tokens     = (const int*)  d_in[0];
    const float* embed      = (const float*)d_in[1];
    const float* attn_theta = (const float*)d_in[2];
    const float* combine_w  = (const float*)d_in[3];
    const float* combine_b  = (const float*)d_in[4];
    const float* ffn_theta  = (const float*)d_in[5];
    const float* lin1_w     = (const float*)d_in[6];
    const float* lin1_b     = (const float*)d_in[7];
    const float* lin2_w     = (const float*)d_in[8];
    const float* lin2_b     = (const float*)d_in[9];
    const float* ln1_g      = (const float*)d_in[10];
    const float* ln1_b      = (const float*)d_in[11];
    const float* ln2_g      = (const float*)d_in[12];
    const float* ln2_b      = (const float*)d_in[13];
    const float* cls_w      = (const float*)d_in[14];
    const float* cls_b      = (const float*)d_in[15];
    float* out = (float*)d_out;

    static int inited = 0;
    if (!inited){
        cudaFuncSetAttribute(k_fused, cudaFuncAttributeMaxDynamicSharedMemorySize, SM_TOT);
        inited = 1;
    }

    k_freq<<<1, 128>>>();
    {
        dim3 ga(256, 2); k_tr_attn<<<ga, 256>>>(combine_w);
        dim3 gf(512, 2); k_tr_ffn<<<gf, 256>>>(lin2_w);
    }
    k_fused<<<NROWS/ROWS, 512, SM_TOT>>>(tokens, embed,
        attn_theta, combine_b, ffn_theta, lin1_w, lin1_b, lin2_b,
        ln1_g, ln1_b, ln2_g, ln2_b);
    k_cls2<<<NBATCH, 256>>>(cls_w, cls_b, out);
}

// round 13
// speedup vs baseline: 1.5216x; 1.5216x over previous
#include <cuda_runtime.h>
#include <cuda_fp16.h>
#include <math.h>
#include <stdint.h>

#define NBATCH 16
#define SEQ    2048
#define EMB    256
#define NROWS  (NBATCH*SEQ)
#define FFND   512
#define ROWS   128
#define XSTR   264       // Xs row stride (halves)
#define ASTR   72        // A/B staging row stride (halves), 144 B: conflict-free ldmatrix

__device__ float  g_freq[128];
__device__ __half g_wt_attn[2*256*256];   // [f][e]
__device__ __half g_wt_ffn[2*256*FFND];   // [e][f]
__device__ float  g_pool[256*EMB];

// ---------------- asm helpers ----------------
__device__ __forceinline__ void mma16(float* d, const uint32_t* a, const uint32_t* b){
    asm volatile("mma.sync.aligned.m16n8k16.row.col.f32.f16.f16.f32 "
        "{%0,%1,%2,%3}, {%4,%5,%6,%7}, {%8,%9}, {%0,%1,%2,%3};"
        : "+f"(d[0]),"+f"(d[1]),"+f"(d[2]),"+f"(d[3])
        : "r"(a[0]),"r"(a[1]),"r"(a[2]),"r"(a[3]),"r"(b[0]),"r"(b[1]));
}
__device__ __forceinline__ void ldsm4(uint32_t& r0, uint32_t& r1, uint32_t& r2, uint32_t& r3,
                                      uint32_t addr){
    asm volatile("ldmatrix.sync.aligned.m8n8.x4.shared.b16 {%0,%1,%2,%3}, [%4];"
        : "=r"(r0),"=r"(r1),"=r"(r2),"=r"(r3) : "r"(addr));
}
__device__ __forceinline__ uint32_t smem_u32(const void* p){
    uint32_t a;
    asm("{ .reg .u64 t; cvta.to.shared.u64 t, %1; cvt.u32.u64 %0, t; }" : "=r"(a) : "l"(p));
    return a;
}
__device__ __forceinline__ void cpasync16(uint32_t dst, const void* src){
    asm volatile("cp.async.cg.shared.global [%0], [%1], 16;" :: "r"(dst), "l"(src));
}
__device__ __forceinline__ void cpcommit(){ asm volatile("cp.async.commit_group;" ::: "memory"); }
__device__ __forceinline__ void cpwait0(){ asm volatile("cp.async.wait_group 0;" ::: "memory"); }

// ---------------- setup kernels ----------------
__global__ void k_freq(){
    int i = threadIdx.x;
    if (i < 128) g_freq[i] = (float)exp(-(double)(2*i) * (log(10000.0) / 256.0));
}
__global__ void k_tr_attn(const float* __restrict__ W){
    int l = blockIdx.y, idx = blockIdx.x*256 + threadIdx.x;
    int e = idx & 255, f = idx >> 8;
    g_wt_attn[l*65536 + f*256 + e] = __float2half_rn(W[l*65536 + e*256 + f]);
}
__global__ void k_tr_ffn(const float* __restrict__ W2){
    int l = blockIdx.y, idx = blockIdx.x*256 + threadIdx.x;
    int f = idx & 511, e = idx >> 9;
    g_wt_ffn[l*131072 + e*512 + f] = __float2half_rn(W2[l*131072 + f*256 + e]);
}

// ---------------- smem layout (bytes) ----------------
// Xs @0       128 x 264 half = 67584
// As @67584   2 x (128 x 72 half = 18432) = 36864
// Bs @104448  2 x (256 x 72 half = 36864) = 73728
// qs @178176  128 x 9 f32 = 4608   -> 182784 total, 1 CTA/SM
// S alias As
#define OFF_AS  67584
#define OFF_BS  104448
#define OFF_QS  178176
#define SM_TOT  182784
#define ABUF    18432u
#define BBUF    36864u

// ---------------- MMA chunk: warp tile 32x64, K=64 (4 k16 steps) ----------------
__device__ __forceinline__ void mma_chunk(uint32_t as_u32, uint32_t bs_u32,
                                          int wm, int wn, int lane,
                                          float acc[2][8][4]){
    int g = lane >> 3, i = lane & 7;
    uint32_t abase = as_u32 + (uint32_t)((wm*32 + (g&1)*8 + i)*144 + (g>>1)*16);
    uint32_t bbase = bs_u32 + (uint32_t)((wn*64 + (g>>1)*8 + i)*144 + (g&1)*16);
    #pragma unroll
    for (int ks = 0; ks < 4; ks++){
        uint32_t a0[4], a1[4], b[4][4];
        ldsm4(a0[0],a0[1],a0[2],a0[3], abase + ks*32);
        ldsm4(a1[0],a1[1],a1[2],a1[3], abase + 16*144 + ks*32);
        #pragma unroll
        for (int p = 0; p < 4; p++)
            ldsm4(b[p][0],b[p][1],b[p][2],b[p][3], bbase + p*16*144 + ks*32);
        #pragma unroll
        for (int p = 0; p < 4; p++){
            mma16(acc[0][2*p],   a0, &b[p][0]);
            mma16(acc[0][2*p+1], a0, &b[p][2]);
            mma16(acc[1][2*p],   a1, &b[p][0]);
            mma16(acc[1][2*p+1], a1, &b[p][2]);
        }
    }
}

// ---------------- staging (512 threads, K=64 chunks) ----------------
// B chunk: 256 n-rows x 64 k halves
__device__ __forceinline__ void stageB_async(uint32_t bs_u32, const __half* __restrict__ Wt,
                                             int rowlen, int koff, int tid){
    #pragma unroll
    for (int i = 0; i < 4; i++){
        int idx = tid + 512*i;
        int seg = idx & 7, n = idx >> 3;
        cpasync16(bs_u32 + (uint32_t)(n*144 + seg*16),
                  Wt + n*rowlen + koff + seg*8);
    }
}
// attn A chunk: As[r][0..63] = cos(Xs[r][kb] + theta), direct store to free buffer
__device__ __forceinline__ void stageA_attn(__half* __restrict__ As,
        const __half* __restrict__ Xs, const float* __restrict__ theta,
        int koff, int tid){
    #pragma unroll
    for (int i = 0; i < 4; i++){
        int idx = tid + 512*i;
        int kk4 = (idx & 15)*4, r = idx >> 4;
        int kb = koff + kk4;
        uint2 xr = *(const uint2*)&Xs[r*XSTR + kb];
        float2 x01 = __half22float2(*(const __half2*)&xr.x);
        float2 x23 = __half22float2(*(const __half2*)&xr.y);
        __half2 h01 = __floats2half2_rn(__cosf(x01.x + __ldg(&theta[(kb+0)&63])),
                                        __cosf(x01.y + __ldg(&theta[(kb+1)&63])));
        __half2 h23 = __floats2half2_rn(__cosf(x23.x + __ldg(&theta[(kb+2)&63])),
                                        __cosf(x23.y + __ldg(&theta[(kb+3)&63])));
        uint2 pk; pk.x = *(const uint32_t*)&h01; pk.y = *(const uint32_t*)&h23;
        *(uint2*)&As[r*ASTR + kk4] = pk;
    }
}
// ffn h chunk: As[r][fcol] = relu(q[r]·W1[:,koff+fcol] + b1), direct store
__device__ __forceinline__ void stageA_ffn(__half* __restrict__ As,
        const float* __restrict__ qs, const float* __restrict__ W1,
        const float* __restrict__ b1, int koff, int tid){
    int fcol = tid & 63, rg = tid >> 6;
    float wcol[8];
    #pragma unroll
    for (int n = 0; n < 8; n++) wcol[n] = __ldg(&W1[n*FFND + koff + fcol]);
    float bf = __ldg(&b1[koff + fcol]);
    #pragma unroll
    for (int rr = 0; rr < 16; rr++){
        int r = rg*16 + rr;
        float a = bf;
        #pragma unroll
        for (int n = 0; n < 8; n++) a += qs[r*9 + n] * wcol[n];
        As[r*ASTR + fcol] = __float2half_rn(fmaxf(a, 0.f));
    }
}

// ---------------- register epilogue: Xs = LN(Xs + D + bias) ----------------
__device__ __forceinline__ void epilogue(__half* __restrict__ Xs, float* __restrict__ S,
        float acc[2][8][4], int wm, int wn, int gid, int tig,
        const float* __restrict__ bias, const float* __restrict__ lng,
        const float* __restrict__ lnb){
    #pragma unroll
    for (int tm = 0; tm < 2; tm++){
        int rl = wm*32 + tm*16 + gid;
        #pragma unroll
        for (int tn = 0; tn < 8; tn++){
            int col = wn*64 + tn*8 + 2*tig;
            float bx = __ldg(&bias[col]), by = __ldg(&bias[col+1]);
            float2 x0 = __half22float2(*(const __half2*)&Xs[rl*XSTR + col]);
            float2 x1 = __half22float2(*(const __half2*)&Xs[(rl+8)*XSTR + col]);
            acc[tm][tn][0] += bx + x0.x; acc[tm][tn][1] += by + x0.y;
            acc[tm][tn][2] += bx + x1.x; acc[tm][tn][3] += by + x1.y;
        }
    }
    float s[2][2], q[2][2];
    #pragma unroll
    for (int tm = 0; tm < 2; tm++){
        s[tm][0] = s[tm][1] = q[tm][0] = q[tm][1] = 0.f;
        #pragma unroll
        for (int tn = 0; tn < 8; tn++){
            s[tm][0] += acc[tm][tn][0] + acc[tm][tn][1];
            q[tm][0] += acc[tm][tn][0]*acc[tm][tn][0] + acc[tm][tn][1]*acc[tm][tn][1];
            s[tm][1] += acc[tm][tn][2] + acc[tm][tn][3];
            q[tm][1] += acc[tm][tn][2]*acc[tm][tn][2] + acc[tm][tn][3]*acc[tm][tn][3];
        }
    }
    #pragma unroll
    for (int off = 1; off <= 2; off <<= 1)
        #pragma unroll
        for (int tm = 0; tm < 2; tm++)
            #pragma unroll
            for (int h = 0; h < 2; h++){
                s[tm][h] += __shfl_xor_sync(0xffffffffu, s[tm][h], off);
                q[tm][h] += __shfl_xor_sync(0xffffffffu, q[tm][h], off);
            }
    if (tig == 0){
        #pragma unroll
        for (int tm = 0; tm < 2; tm++){
            int rl = wm*32 + tm*16 + gid;
            S[rl*8 + wn*2]        = s[tm][0];
            S[rl*8 + wn*2 + 1]    = q[tm][0];
            S[(rl+8)*8 + wn*2]    = s[tm][1];
            S[(rl+8)*8 + wn*2 +1] = q[tm][1];
        }
    }
    __syncthreads();
    #pragma unroll
    for (int tm = 0; tm < 2; tm++){
        int rl = wm*32 + tm*16 + gid;
        #pragma unroll
        for (int h = 0; h < 2; h++){
            int r = rl + 8*h;
            float Ss = S[r*8+0] + S[r*8+2] + S[r*8+4] + S[r*8+6];
            float Qq = S[r*8+1] + S[r*8+3] + S[r*8+5] + S[r*8+7];
            float m  = Ss * (1.f/256.f);
            float var = fmaxf(Qq * (1.f/256.f) - m*m, 0.f);
            float rs = rsqrtf(var + 1e-5f);
            #pragma unroll
            for (int tn = 0; tn < 8; tn++){
                int col = wn*64 + tn*8 + 2*tig;
                float z0 = acc[tm][tn][2*h], z1 = acc[tm][tn][2*h+1];
                *(__half2*)&Xs[r*XSTR + col] =
                    __floats2half2_rn((z0-m)*rs*__ldg(&lng[col]) + __ldg(&lnb[col]),
                                      (z1-m)*rs*__ldg(&lng[col+1]) + __ldg(&lnb[col+1]));
            }
        }
    }
}

// ---------------- fused kernel ----------------
__global__ __launch_bounds__(512, 1) void k_fused(
    const int* __restrict__ tokens, const float* __restrict__ embed,
    const float* __restrict__ attn_theta, const float* __restrict__ combine_b,
    const float* __restrict__ ffn_theta,  const float* __restrict__ lin1_w,
    const float* __restrict__ lin1_b,     const float* __restrict__ lin2_b,
    const float* __restrict__ ln1g, const float* __restrict__ ln1b,
    const float* __restrict__ ln2g, const float* __restrict__ ln2b)
{
    extern __shared__ char sm[];
    __half* Xs  = (__half*)sm;
    __half* As  = (__half*)(sm + OFF_AS);
    __half* Bs  = (__half*)(sm + OFF_BS);
    float*  qs  = (float*)(sm + OFF_QS);
    float*  S   = (float*)(sm + OFF_AS);   // alias (post-GEMM only)
    uint32_t as_u32 = smem_u32(As);
    uint32_t bs_u32 = smem_u32(Bs);

    int tid = threadIdx.x, lane = tid & 31, wid = tid >> 5;
    int gid = lane >> 2, tig = lane & 3;
    int wm = wid & 3, wn = wid >> 2;    // 4m x 4n, warp tile 32 x 64
    int row0 = blockIdx.x * ROWS;

    // ---- embed + positional encoding (fp16 Xs) ----
    #pragma unroll 4
    for (int i = 0; i < 16; i++){
        int idx = tid + 512*i;
        int r = idx >> 6, c4 = (idx & 63) * 4;
        int tok = __ldg(&tokens[row0 + r]);
        float4 v = *(const float4*)&embed[tok*EMB + c4];
        float pos = (float)((row0 + r) & (SEQ-1));
        float s0,c0,s1,c1;
        sincosf(pos * g_freq[(c4>>1)+0], &s0, &c0);
        sincosf(pos * g_freq[(c4>>1)+1], &s1, &c1);
        __half2 lo = __floats2half2_rn(v.x + s0, v.y + c0);
        __half2 hi = __floats2half2_rn(v.z + s1, v.w + c1);
        uint2 pk; pk.x = *(const uint32_t*)&lo; pk.y = *(const uint32_t*)&hi;
        *(uint2*)&Xs[r*XSTR + c4] = pk;
    }
    __syncthreads();

    #pragma unroll 1
    for (int l = 0; l < 2; l++){
        // ================= attention: 4 K-chunks of 64 =================
        {
            const float*  theta = attn_theta + l*64;
            const __half* Wt    = g_wt_attn + l*65536;
            float acc[2][8][4];
            float* ap = &acc[0][0][0];
            #pragma unroll
            for (int j = 0; j < 64; j++) ap[j] = 0.f;

            stageB_async(bs_u32, Wt, 256, 0, tid);
            cpcommit();
            stageA_attn(As, Xs, theta, 0, tid);
            cpwait0(); __syncthreads();

            #pragma unroll 1
            for (int c = 0; c < 4; c++){
                int cur = c & 1, nxt = cur ^ 1;
                if (c + 1 < 4){
                    stageB_async(bs_u32 + nxt*BBUF, Wt, 256, (c+1)*64, tid);
                    cpcommit();
                }
                mma_chunk(as_u32 + cur*ABUF, bs_u32 + cur*BBUF, wm, wn, lane, acc);
                if (c + 1 < 4){
                    stageA_attn(As + nxt*(ABUF/2), Xs, theta, (c+1)*64, tid);
                    cpwait0();
                }
                __syncthreads();
            }
            epilogue(Xs, S, acc, wm, wn, gid, tig,
                     combine_b + l*256, ln1g + l*256, ln1b + l*256);
            __syncthreads();
        }
        // ================= ffn: 8 K-chunks of 64 =================
        {
            const float*  fth = ffn_theta + l*8;
            const float*  W1  = lin1_w + l*8*FFND;
            const float*  b1  = lin1_b + l*FFND;
            const __half* Wt2 = g_wt_ffn + l*256*FFND;
            float acc[2][8][4];
            float* ap = &acc[0][0][0];
            #pragma unroll
            for (int j = 0; j < 64; j++) ap[j] = 0.f;

            for (int idx = tid; idx < ROWS*8; idx += 512){
                int r = idx >> 3, n = idx & 7;
                qs[r*9 + n] = __cosf(__half2float(Xs[r*XSTR + n])) * __cosf(__ldg(&fth[n]));
            }
            stageB_async(bs_u32, Wt2, 512, 0, tid);
            cpcommit();
            __syncthreads();
            stageA_ffn(As, qs, W1, b1, 0, tid);
            cpwait0(); __syncthreads();

            #pragma unroll 1
            for (int c = 0; c < 8; c++){
                int cur = c & 1, nxt = cur ^ 1;
                if (c + 1 < 8){
                    stageB_async(bs_u32 + nxt*BBUF, Wt2, 512, (c+1)*64, tid);
                    cpcommit();
                }
                mma_chunk(as_u32 + cur*ABUF, bs_u32 + cur*BBUF, wm, wn, lane, acc);
                if (c + 1 < 8){
                    stageA_ffn(As + nxt*(ABUF/2), qs, W1, b1, (c+1)*64, tid);
                    cpwait0();
                }
                __syncthreads();
            }
            epilogue(Xs, S, acc, wm, wn, gid, tig,
                     lin2_b + l*256, ln2g + l*256, ln2b + l*256);
            __syncthreads();
        }
    }

    // ---- partial pool: column sums over this CTA's 128 rows ----
    {
        int col = tid & 255, half = tid >> 8;
        float s = 0.f;
        #pragma unroll 8
        for (int r = half*64; r < half*64 + 64; r++) s += __half2float(Xs[r*XSTR + col]);
        float* P = (float*)(sm + OFF_AS);
        P[half*256 + col] = s;
        __syncthreads();
        if (tid < 256)
            g_pool[blockIdx.x*256 + tid] = P[tid] + P[256 + tid];
    }
}

// ---------------- classifier ----------------
__global__ void k_cls2(const float* __restrict__ cw, const float* __restrict__ cb,
                       float* __restrict__ out){
    int b = blockIdx.x, tid = threadIdx.x;
    float s = 0.f;
    #pragma unroll
    for (int seg = 0; seg < 16; seg++) s += g_pool[(b*16+seg)*256 + tid];
    float p = s * (1.f/(float)SEQ);
    float l0 = p * cw[tid*2 + 0];
    float l1 = p * cw[tid*2 + 1];
    #pragma unroll
    for (int off=16; off; off>>=1){
        l0 += __shfl_xor_sync(0xffffffffu, l0, off);
        l1 += __shfl_xor_sync(0xffffffffu, l1, off);
    }
    __shared__ float r0[8], r1[8];
    int warp = tid >> 5, lane = tid & 31;
    if (lane == 0){ r0[warp] = l0; r1[warp] = l1; }
    __syncthreads();
    if (tid == 0){
        float a = cb[0], c = cb[1];
        #pragma unroll
        for (int w = 0; w < 8; w++){ a += r0[w]; c += r1[w]; }
        out[b*2 + 0] = a; out[b*2 + 1] = c;
    }
}

// ---------------- launch ----------------
extern "C" void kernel_launch(void* const* d_in, const int* in_sizes, int n_in,
                              void* d_out, int out_size){
    const int*   tokens     = (const int*)  d_in[0];
    const float* embed      = (const float*)d_in[1];
    const float* attn_theta = (const float*)d_in[2];
    const float* combine_w  = (const float*)d_in[3];
    const float* combine_b  = (const float*)d_in[4];
    const float* ffn_theta  = (const float*)d_in[5];
    const float* lin1_w     = (const float*)d_in[6];
    const float* lin1_b     = (const float*)d_in[7];
    const float* lin2_w     = (const float*)d_in[8];
    const float* lin2_b     = (const float*)d_in[9];
    const float* ln1_g      = (const float*)d_in[10];
    const float* ln1_b      = (const float*)d_in[11];
    const float* ln2_g      = (const float*)d_in[12];
    const float* ln2_b      = (const float*)d_in[13];
    const float* cls_w      = (const float*)d_in[14];
    const float* cls_b      = (const float*)d_in[15];
    float* out = (float*)d_out;

    static int inited = 0;
    if (!inited){
        cudaFuncSetAttribute(k_fused, cudaFuncAttributeMaxDynamicSharedMemorySize, SM_TOT);
        inited = 1;
    }

    k_freq<<<1, 128>>>();
    {
        dim3 ga(256, 2); k_tr_attn<<<ga, 256>>>(combine_w);
        dim3 gf(512, 2); k_tr_ffn<<<gf, 256>>>(lin2_w);
    }
    k_fused<<<NROWS/ROWS, 512, SM_TOT>>>(tokens, embed,
        attn_theta, combine_b, ffn_theta, lin1_w, lin1_b, lin2_b,
        ln1_g, ln1_b, ln2_g, ln2_b);
    k_cls2<<<NBATCH, 256>>>(cls_w, cls_b, out);
}

// round 14
// speedup vs baseline: 1.6247x; 1.0678x over previous
#include <cuda_runtime.h>
#include <cuda_fp16.h>
#include <math.h>
#include <stdint.h>

#define NBATCH 16
#define SEQ    2048
#define EMB    256
#define NROWS  (NBATCH*SEQ)
#define FFND   512
#define ROWS   128
#define XSTR   264       // Xs row stride (halves)
#define ASTR   72        // staging row stride (halves), 144 B

__device__ float  g_freq[128];
__device__ __half g_wt_attn[2*256*256];   // [f][e]
__device__ __half g_wt_ffn[2*256*FFND];   // [e][f]
__device__ float  g_pool[256*EMB];

// ---------------- asm helpers ----------------
__device__ __forceinline__ void mma16(float* d, const uint32_t* a, const uint32_t* b){
    asm volatile("mma.sync.aligned.m16n8k16.row.col.f32.f16.f16.f32 "
        "{%0,%1,%2,%3}, {%4,%5,%6,%7}, {%8,%9}, {%0,%1,%2,%3};"
        : "+f"(d[0]),"+f"(d[1]),"+f"(d[2]),"+f"(d[3])
        : "r"(a[0]),"r"(a[1]),"r"(a[2]),"r"(a[3]),"r"(b[0]),"r"(b[1]));
}
__device__ __forceinline__ void ldsm4(uint32_t& r0, uint32_t& r1, uint32_t& r2, uint32_t& r3,
                                      uint32_t addr){
    asm volatile("ldmatrix.sync.aligned.m8n8.x4.shared.b16 {%0,%1,%2,%3}, [%4];"
        : "=r"(r0),"=r"(r1),"=r"(r2),"=r"(r3) : "r"(addr));
}
__device__ __forceinline__ uint32_t smem_u32(const void* p){
    uint32_t a;
    asm("{ .reg .u64 t; cvta.to.shared.u64 t, %1; cvt.u32.u64 %0, t; }" : "=r"(a) : "l"(p));
    return a;
}
__device__ __forceinline__ void cpasync16(uint32_t dst, const void* src){
    asm volatile("cp.async.cg.shared.global [%0], [%1], 16;" :: "r"(dst), "l"(src));
}
__device__ __forceinline__ void cpcommit(){ asm volatile("cp.async.commit_group;" ::: "memory"); }
__device__ __forceinline__ void cpwait0(){ asm volatile("cp.async.wait_group 0;" ::: "memory"); }

// ---------------- setup kernels ----------------
__global__ void k_freq(){
    int i = threadIdx.x;
    if (i < 128) g_freq[i] = (float)exp(-(double)(2*i) * (log(10000.0) / 256.0));
}
__global__ void k_tr_attn(const float* __restrict__ W){
    int l = blockIdx.y, idx = blockIdx.x*256 + threadIdx.x;
    int e = idx & 255, f = idx >> 8;
    g_wt_attn[l*65536 + f*256 + e] = __float2half_rn(W[l*65536 + e*256 + f]);
}
__global__ void k_tr_ffn(const float* __restrict__ W2){
    int l = blockIdx.y, idx = blockIdx.x*256 + threadIdx.x;
    int f = idx & 511, e = idx >> 9;
    g_wt_ffn[l*131072 + e*512 + f] = __float2half_rn(W2[l*131072 + f*256 + e]);
}

// ---------------- smem layout (bytes) ----------------
// Xs  @0       128 x 264 half = 67584
// As  @67584   2 x (128 x 72 half = 18432) = 36864
// Bs  @104448  2 x (256 x 72 half = 36864) = 73728
// qs  @178176  128 x 9 f32 = 4608
// W1s @182784  8 x 512 f32 = 16384  -> 199168 total, 1 CTA/SM
// S alias As
#define OFF_AS  67584
#define OFF_BS  104448
#define OFF_QS  178176
#define OFF_W1  182784
#define SM_TOT  199168
#define ABUF    18432u
#define BBUF    36864u

// ---------------- MMA chunk: warp tile 32x64, K=64 ----------------
__device__ __forceinline__ void mma_chunk(uint32_t as_u32, uint32_t bs_u32,
                                          int wm, int wn, int lane,
                                          float acc[2][8][4]){
    int g = lane >> 3, i = lane & 7;
    uint32_t abase = as_u32 + (uint32_t)((wm*32 + (g&1)*8 + i)*144 + (g>>1)*16);
    uint32_t bbase = bs_u32 + (uint32_t)((wn*64 + (g>>1)*8 + i)*144 + (g&1)*16);
    #pragma unroll
    for (int ks = 0; ks < 4; ks++){
        uint32_t a0[4], a1[4], b[4][4];
        ldsm4(a0[0],a0[1],a0[2],a0[3], abase + ks*32);
        ldsm4(a1[0],a1[1],a1[2],a1[3], abase + 16*144 + ks*32);
        #pragma unroll
        for (int p = 0; p < 4; p++)
            ldsm4(b[p][0],b[p][1],b[p][2],b[p][3], bbase + p*16*144 + ks*32);
        #pragma unroll
        for (int p = 0; p < 4; p++){
            mma16(acc[0][2*p],   a0, &b[p][0]);
            mma16(acc[0][2*p+1], a0, &b[p][2]);
            mma16(acc[1][2*p],   a1, &b[p][0]);
            mma16(acc[1][2*p+1], a1, &b[p][2]);
        }
    }
}

// ---------------- staging (512 threads, K=64 chunks) ----------------
__device__ __forceinline__ void stageB_async(uint32_t bs_u32, const __half* __restrict__ Wt,
                                             int rowlen, int koff, int tid){
    #pragma unroll
    for (int i = 0; i < 4; i++){
        int idx = tid + 512*i;
        int seg = idx & 7, n = idx >> 3;
        cpasync16(bs_u32 + (uint32_t)(n*144 + seg*16),
                  Wt + n*rowlen + koff + seg*8);
    }
}
// attn A: compute cos into regs (8 regs = 16 halves)
__device__ __forceinline__ void attnA_regs(const __half* __restrict__ Xs,
        const float* __restrict__ theta, int koff, int tid, uint2* av){
    #pragma unroll
    for (int i = 0; i < 4; i++){
        int idx = tid + 512*i;
        int kk4 = (idx & 15)*4, r = idx >> 4;
        int kb = koff + kk4;
        uint2 xr = *(const uint2*)&Xs[r*XSTR + kb];
        float2 x01 = __half22float2(*(const __half2*)&xr.x);
        float2 x23 = __half22float2(*(const __half2*)&xr.y);
        __half2 h01 = __floats2half2_rn(__cosf(x01.x + __ldg(&theta[(kb+0)&63])),
                                        __cosf(x01.y + __ldg(&theta[(kb+1)&63])));
        __half2 h23 = __floats2half2_rn(__cosf(x23.x + __ldg(&theta[(kb+2)&63])),
                                        __cosf(x23.y + __ldg(&theta[(kb+3)&63])));
        av[i].x = *(const uint32_t*)&h01;
        av[i].y = *(const uint32_t*)&h23;
    }
}
__device__ __forceinline__ void attnA_sts(__half* __restrict__ As, int tid, const uint2* av){
    #pragma unroll
    for (int i = 0; i < 4; i++){
        int idx = tid + 512*i;
        int kk4 = (idx & 15)*4, r = idx >> 4;
        *(uint2*)&As[r*ASTR + kk4] = av[i];
    }
}
// ffn h: column-pair per thread, 8 rows; compute into 8 packed half2 regs
__device__ __forceinline__ void ffnA_regs(const float* __restrict__ qs,
        const float* __restrict__ W1s, const float* __restrict__ b1,
        int koff, int tid, uint32_t* hv2){
    int fc = (tid & 31)*2, rg = tid >> 5;   // 16 groups of 8 rows
    float w0[8], w1[8];
    #pragma unroll
    for (int n = 0; n < 8; n++){
        w0[n] = W1s[n*FFND + koff + fc];
        w1[n] = W1s[n*FFND + koff + fc + 1];
    }
    float b0 = __ldg(&b1[koff + fc]), b1v = __ldg(&b1[koff + fc + 1]);
    #pragma unroll
    for (int rr = 0; rr < 8; rr++){
        int r = rg*8 + rr;
        float a0 = b0, a1 = b1v;
        #pragma unroll
        for (int n = 0; n < 8; n++){
            float qv = qs[r*9 + n];
            a0 += qv * w0[n]; a1 += qv * w1[n];
        }
        __half2 h = __floats2half2_rn(fmaxf(a0, 0.f), fmaxf(a1, 0.f));
        hv2[rr] = *(const uint32_t*)&h;
    }
}
__device__ __forceinline__ void ffnA_sts(__half* __restrict__ As, int tid, const uint32_t* hv2){
    int fc = (tid & 31)*2, rg = tid >> 5;
    #pragma unroll
    for (int rr = 0; rr < 8; rr++)
        *(uint32_t*)&As[(rg*8+rr)*ASTR + fc] = hv2[rr];
}

// ---------------- register epilogue: Xs = LN(Xs + D + bias) ----------------
__device__ __forceinline__ void epilogue(__half* __restrict__ Xs, float* __restrict__ S,
        float acc[2][8][4], int wm, int wn, int gid, int tig,
        const float* __restrict__ bias, const float* __restrict__ lng,
        const float* __restrict__ lnb){
    #pragma unroll
    for (int tm = 0; tm < 2; tm++){
        int rl = wm*32 + tm*16 + gid;
        #pragma unroll
        for (int tn = 0; tn < 8; tn++){
            int col = wn*64 + tn*8 + 2*tig;
            float bx = __ldg(&bias[col]), by = __ldg(&bias[col+1]);
            float2 x0 = __half22float2(*(const __half2*)&Xs[rl*XSTR + col]);
            float2 x1 = __half22float2(*(const __half2*)&Xs[(rl+8)*XSTR + col]);
            acc[tm][tn][0] += bx + x0.x; acc[tm][tn][1] += by + x0.y;
            acc[tm][tn][2] += bx + x1.x; acc[tm][tn][3] += by + x1.y;
        }
    }
    float s[2][2], q[2][2];
    #pragma unroll
    for (int tm = 0; tm < 2; tm++){
        s[tm][0] = s[tm][1] = q[tm][0] = q[tm][1] = 0.f;
        #pragma unroll
        for (int tn = 0; tn < 8; tn++){
            s[tm][0] += acc[tm][tn][0] + acc[tm][tn][1];
            q[tm][0] += acc[tm][tn][0]*acc[tm][tn][0] + acc[tm][tn][1]*acc[tm][tn][1];
            s[tm][1] += acc[tm][tn][2] + acc[tm][tn][3];
            q[tm][1] += acc[tm][tn][2]*acc[tm][tn][2] + acc[tm][tn][3]*acc[tm][tn][3];
        }
    }
    #pragma unroll
    for (int off = 1; off <= 2; off <<= 1)
        #pragma unroll
        for (int tm = 0; tm < 2; tm++)
            #pragma unroll
            for (int h = 0; h < 2; h++){
                s[tm][h] += __shfl_xor_sync(0xffffffffu, s[tm][h], off);
                q[tm][h] += __shfl_xor_sync(0xffffffffu, q[tm][h], off);
            }
    if (tig == 0){
        #pragma unroll
        for (int tm = 0; tm < 2; tm++){
            int rl = wm*32 + tm*16 + gid;
            S[rl*8 + wn*2]        = s[tm][0];
            S[rl*8 + wn*2 + 1]    = q[tm][0];
            S[(rl+8)*8 + wn*2]    = s[tm][1];
            S[(rl+8)*8 + wn*2 +1] = q[tm][1];
        }
    }
    __syncthreads();
    #pragma unroll
    for (int tm = 0; tm < 2; tm++){
        int rl = wm*32 + tm*16 + gid;
        #pragma unroll
        for (int h = 0; h < 2; h++){
            int r = rl + 8*h;
            float Ss = S[r*8+0] + S[r*8+2] + S[r*8+4] + S[r*8+6];
            float Qq = S[r*8+1] + S[r*8+3] + S[r*8+5] + S[r*8+7];
            float m  = Ss * (1.f/256.f);
            float var = fmaxf(Qq * (1.f/256.f) - m*m, 0.f);
            float rs = rsqrtf(var + 1e-5f);
            #pragma unroll
            for (int tn = 0; tn < 8; tn++){
                int col = wn*64 + tn*8 + 2*tig;
                float z0 = acc[tm][tn][2*h], z1 = acc[tm][tn][2*h+1];
                *(__half2*)&Xs[r*XSTR + col] =
                    __floats2half2_rn((z0-m)*rs*__ldg(&lng[col]) + __ldg(&lnb[col]),
                                      (z1-m)*rs*__ldg(&lng[col+1]) + __ldg(&lnb[col+1]));
            }
        }
    }
}

// ---------------- fused kernel ----------------
__global__ __launch_bounds__(512, 1) void k_fused(
    const int* __restrict__ tokens, const float* __restrict__ embed,
    const float* __restrict__ attn_theta, const float* __restrict__ combine_b,
    const float* __restrict__ ffn_theta,  const float* __restrict__ lin1_w,
    const float* __restrict__ lin1_b,     const float* __restrict__ lin2_b,
    const float* __restrict__ ln1g, const float* __restrict__ ln1b,
    const float* __restrict__ ln2g, const float* __restrict__ ln2b)
{
    extern __shared__ char sm[];
    __half* Xs  = (__half*)sm;
    __half* As  = (__half*)(sm + OFF_AS);
    __half* Bs  = (__half*)(sm + OFF_BS);
    float*  qs  = (float*)(sm + OFF_QS);
    float*  W1s = (float*)(sm + OFF_W1);
    float*  S   = (float*)(sm + OFF_AS);   // alias (post-GEMM only)
    uint32_t as_u32 = smem_u32(As);
    uint32_t bs_u32 = smem_u32(Bs);

    int tid = threadIdx.x, lane = tid & 31, wid = tid >> 5;
    int gid = lane >> 2, tig = lane & 3;
    int wm = wid & 3, wn = wid >> 2;    // 4m x 4n, warp tile 32 x 64
    int row0 = blockIdx.x * ROWS;

    // ---- embed + positional encoding (fp16 Xs) ----
    #pragma unroll 4
    for (int i = 0; i < 16; i++){
        int idx = tid + 512*i;
        int r = idx >> 6, c4 = (idx & 63) * 4;
        int tok = __ldg(&tokens[row0 + r]);
        float4 v = *(const float4*)&embed[tok*EMB + c4];
        float pos = (float)((row0 + r) & (SEQ-1));
        float s0,c0,s1,c1;
        sincosf(pos * g_freq[(c4>>1)+0], &s0, &c0);
        sincosf(pos * g_freq[(c4>>1)+1], &s1, &c1);
        __half2 lo = __floats2half2_rn(v.x + s0, v.y + c0);
        __half2 hi = __floats2half2_rn(v.z + s1, v.w + c1);
        uint2 pk; pk.x = *(const uint32_t*)&lo; pk.y = *(const uint32_t*)&hi;
        *(uint2*)&Xs[r*XSTR + c4] = pk;
    }
    __syncthreads();

    #pragma unroll 1
    for (int l = 0; l < 2; l++){
        // ================= attention: 4 K-chunks of 64 =================
        {
            const float*  theta = attn_theta + l*64;
            const __half* Wt    = g_wt_attn + l*65536;
            float acc[2][8][4];
            float* ap = &acc[0][0][0];
            #pragma unroll
            for (int j = 0; j < 64; j++) ap[j] = 0.f;

            uint2 av[4];
            attnA_regs(Xs, theta, 0, tid, av);
            stageB_async(bs_u32, Wt, 256, 0, tid);
            cpcommit();
            attnA_sts(As, tid, av);
            cpwait0(); __syncthreads();

            #pragma unroll 1
            for (int c = 0; c < 4; c++){
                int cur = c & 1, nxt = cur ^ 1;
                if (c + 1 < 4){
                    stageB_async(bs_u32 + nxt*BBUF, Wt, 256, (c+1)*64, tid);
                    cpcommit();
                    attnA_regs(Xs, theta, (c+1)*64, tid, av);
                }
                mma_chunk(as_u32 + cur*ABUF, bs_u32 + cur*BBUF, wm, wn, lane, acc);
                if (c + 1 < 4){
                    attnA_sts(As + nxt*(ABUF/2), tid, av);
                    cpwait0();
                }
                __syncthreads();
            }
            epilogue(Xs, S, acc, wm, wn, gid, tig,
                     combine_b + l*256, ln1g + l*256, ln1b + l*256);
            __syncthreads();
        }
        // ================= ffn: 8 K-chunks of 64 =================
        {
            const float*  fth = ffn_theta + l*8;
            const float*  W1  = lin1_w + l*8*FFND;
            const float*  b1  = lin1_b + l*FFND;
            const __half* Wt2 = g_wt_ffn + l*256*FFND;
            float acc[2][8][4];
            float* ap = &acc[0][0][0];
            #pragma unroll
            for (int j = 0; j < 64; j++) ap[j] = 0.f;

            for (int idx = tid; idx < ROWS*8; idx += 512){
                int r = idx >> 3, n = idx & 7;
                qs[r*9 + n] = __cosf(__half2float(Xs[r*XSTR + n])) * __cosf(__ldg(&fth[n]));
            }
            {
                const float4* src = (const float4*)W1;
                float4* dst = (float4*)W1s;
                #pragma unroll
                for (int i = 0; i < 2; i++) dst[tid + 512*i] = src[tid + 512*i];
            }
            stageB_async(bs_u32, Wt2, 512, 0, tid);
            cpcommit();
            __syncthreads();
            uint32_t hv2[8];
            ffnA_regs(qs, W1s, b1, 0, tid, hv2);
            ffnA_sts(As, tid, hv2);
            cpwait0(); __syncthreads();

            #pragma unroll 1
            for (int c = 0; c < 8; c++){
                int cur = c & 1, nxt = cur ^ 1;
                if (c + 1 < 8){
                    stageB_async(bs_u32 + nxt*BBUF, Wt2, 512, (c+1)*64, tid);
                    cpcommit();
                    ffnA_regs(qs, W1s, b1, (c+1)*64, tid, hv2);
                }
                mma_chunk(as_u32 + cur*ABUF, bs_u32 + cur*BBUF, wm, wn, lane, acc);
                if (c + 1 < 8){
                    ffnA_sts(As + nxt*(ABUF/2), tid, hv2);
                    cpwait0();
                }
                __syncthreads();
            }
            epilogue(Xs, S, acc, wm, wn, gid, tig,
                     lin2_b + l*256, ln2g + l*256, ln2b + l*256);
            __syncthreads();
        }
    }

    // ---- partial pool: column sums over this CTA's 128 rows ----
    {
        int col = tid & 255, half = tid >> 8;
        float s = 0.f;
        #pragma unroll 8
        for (int r = half*64; r < half*64 + 64; r++) s += __half2float(Xs[r*XSTR + col]);
        float* P = (float*)(sm + OFF_AS);
        P[half*256 + col] = s;
        __syncthreads();
        if (tid < 256)
            g_pool[blockIdx.x*256 + tid] = P[tid] + P[256 + tid];
    }
}

// ---------------- classifier ----------------
__global__ void k_cls2(const float* __restrict__ cw, const float* __restrict__ cb,
                       float* __restrict__ out){
    int b = blockIdx.x, tid = threadIdx.x;
    float s = 0.f;
    #pragma unroll
    for (int seg = 0; seg < 16; seg++) s += g_pool[(b*16+seg)*256 + tid];
    float p = s * (1.f/(float)SEQ);
    float l0 = p * cw[tid*2 + 0];
    float l1 = p * cw[tid*2 + 1];
    #pragma unroll
    for (int off=16; off; off>>=1){
        l0 += __shfl_xor_sync(0xffffffffu, l0, off);
        l1 += __shfl_xor_sync(0xffffffffu, l1, off);
    }
    __shared__ float r0[8], r1[8];
    int warp = tid >> 5, lane = tid & 31;
    if (lane == 0){ r0[warp] = l0; r1[warp] = l1; }
    __syncthreads();
    if (tid == 0){
        float a = cb[0], c = cb[1];
        #pragma unroll
        for (int w = 0; w < 8; w++){ a += r0[w]; c += r1[w]; }
        out[b*2 + 0] = a; out[b*2 + 1] = c;
    }
}

// ---------------- launch ----------------
extern "C" void kernel_launch(void* const* d_in, const int* in_sizes, int n_in,
                              void* d_out, int out_size){
    const int*   tokens     = (const int*)  d_in[0];
    const float* embed      = (const float*)d_in[1];
    const float* attn_theta = (const float*)d_in[2];
    const float* combine_w  = (const float*)d_in[3];
    const float* combine_b  = (const float*)d_in[4];
    const float* ffn_theta  = (const float*)d_in[5];
    const float* lin1_w     = (const float*)d_in[6];
    const float* lin1_b     = (const float*)d_in[7];
    const float* lin2_w     = (const float*)d_in[8];
    const float* lin2_b     = (const float*)d_in[9];
    const float* ln1_g      = (const float*)d_in[10];
    const float* ln1_b      = (const float*)d_in[11];
    const float* ln2_g      = (const float*)d_in[12];
    const float* ln2_b      = (const float*)d_in[13];
    const float* cls_w      = (const float*)d_in[14];
    const float* cls_b      = (const float*)d_in[15];
    float* out = (float*)d_out;

    static int inited = 0;
    if (!inited){
        cudaFuncSetAttribute(k_fused, cudaFuncAttributeMaxDynamicSharedMemorySize, SM_TOT);
        inited = 1;
    }

    k_freq<<<1, 128>>>();
    {
        dim3 ga(256, 2); k_tr_attn<<<ga, 256>>>(combine_w);
        dim3 gf(512, 2); k_tr_ffn<<<gf, 256>>>(lin2_w);
    }
    k_fused<<<NROWS/ROWS, 512, SM_TOT>>>(tokens, embed,
        attn_theta, combine_b, ffn_theta, lin1_w, lin1_b, lin2_b,
        ln1_g, ln1_b, ln2_g, ln2_b);
    k_cls2<<<NBATCH, 256>>>(cls_w, cls_b, out);
}

// round 15
// speedup vs baseline: 1.6293x; 1.0029x over previous
#include <cuda_runtime.h>
#include <cuda_fp16.h>
#include <math.h>
#include <stdint.h>

#define NBATCH 16
#define SEQ    2048
#define EMB    256
#define NROWS  (NBATCH*SEQ)
#define FFND   512
#define ROWS   128
#define XSTR   264       // Xs / A-full row stride (halves), 528 B

__device__ float  g_freq[128];
__device__ __half g_wt_attn[2*256*256];   // [f][e]
__device__ __half g_wt_ffn[2*256*FFND];   // [e][f]
__device__ float  g_pool[256*EMB];

// ---------------- asm helpers ----------------
__device__ __forceinline__ void mma16(float* d, const uint32_t* a, const uint32_t* b){
    asm volatile("mma.sync.aligned.m16n8k16.row.col.f32.f16.f16.f32 "
        "{%0,%1,%2,%3}, {%4,%5,%6,%7}, {%8,%9}, {%0,%1,%2,%3};"
        : "+f"(d[0]),"+f"(d[1]),"+f"(d[2]),"+f"(d[3])
        : "r"(a[0]),"r"(a[1]),"r"(a[2]),"r"(a[3]),"r"(b[0]),"r"(b[1]));
}
__device__ __forceinline__ void ldsm4(uint32_t& r0, uint32_t& r1, uint32_t& r2, uint32_t& r3,
                                      uint32_t addr){
    asm volatile("ldmatrix.sync.aligned.m8n8.x4.shared.b16 {%0,%1,%2,%3}, [%4];"
        : "=r"(r0),"=r"(r1),"=r"(r2),"=r"(r3) : "r"(addr));
}
__device__ __forceinline__ uint32_t smem_u32(const void* p){
    uint32_t a;
    asm("{ .reg .u64 t; cvta.to.shared.u64 t, %1; cvt.u32.u64 %0, t; }" : "=r"(a) : "l"(p));
    return a;
}
__device__ __forceinline__ void cpasync16(uint32_t dst, const void* src){
    asm volatile("cp.async.cg.shared.global [%0], [%1], 16;" :: "r"(dst), "l"(src));
}
__device__ __forceinline__ void cpcommit(){ asm volatile("cp.async.commit_group;" ::: "memory"); }
__device__ __forceinline__ void cpwait0(){ asm volatile("cp.async.wait_group 0;" ::: "memory"); }

// ---------------- setup kernels ----------------
__global__ void k_freq(){
    int i = threadIdx.x;
    if (i < 128) g_freq[i] = (float)exp(-(double)(2*i) * (log(10000.0) / 256.0));
}
__global__ void k_tr_attn(const float* __restrict__ W){
    int l = blockIdx.y, idx = blockIdx.x*256 + threadIdx.x;
    int e = idx & 255, f = idx >> 8;
    g_wt_attn[l*65536 + f*256 + e] = __float2half_rn(W[l*65536 + e*256 + f]);
}
__global__ void k_tr_ffn(const float* __restrict__ W2){
    int l = blockIdx.y, idx = blockIdx.x*256 + threadIdx.x;
    int f = idx & 511, e = idx >> 9;
    g_wt_ffn[l*131072 + e*512 + f] = __float2half_rn(W2[l*131072 + f*256 + e]);
}

// ---------------- smem layout (bytes) ----------------
// Xs  @0       128 x 264 half = 67584
// Af  @67584   128 x 264 half = 67584   (full A / h K-half, stride 264)
// Bs  @135168  2 x (256 x 72 half = 36864) = 73728
// qs  @208896  128 x 9 f32 = 4608  -> 213504 total, 1 CTA/SM
// S / P alias Af (post-GEMM only)
#define OFF_AF  67584
#define OFF_BS  135168
#define OFF_QS  208896
#define SM_TOT  213504
#define BBUF    36864u

// ---------------- MMA chunk: warp tile 32x64, K=64, A from full buffer ----------------
__device__ __forceinline__ void mma_chunk(uint32_t af_u32, uint32_t bs_u32,
                                          int wm, int wn, int lane,
                                          float acc[2][8][4]){
    int g = lane >> 3, i = lane & 7;
    uint32_t abase = af_u32 + (uint32_t)((wm*32 + (g&1)*8 + i)*528 + (g>>1)*16);
    uint32_t bbase = bs_u32 + (uint32_t)((wn*64 + (g>>1)*8 + i)*144 + (g&1)*16);
    #pragma unroll
    for (int ks = 0; ks < 4; ks++){
        uint32_t a0[4], a1[4], b[4][4];
        ldsm4(a0[0],a0[1],a0[2],a0[3], abase + ks*32);
        ldsm4(a1[0],a1[1],a1[2],a1[3], abase + 16*528 + ks*32);
        #pragma unroll
        for (int p = 0; p < 4; p++)
            ldsm4(b[p][0],b[p][1],b[p][2],b[p][3], bbase + p*16*144 + ks*32);
        #pragma unroll
        for (int p = 0; p < 4; p++){
            mma16(acc[0][2*p],   a0, &b[p][0]);
            mma16(acc[0][2*p+1], a0, &b[p][2]);
            mma16(acc[1][2*p],   a1, &b[p][0]);
            mma16(acc[1][2*p+1], a1, &b[p][2]);
        }
    }
}

// ---------------- staging (512 threads) ----------------
__device__ __forceinline__ void stageB_async(uint32_t bs_u32, const __half* __restrict__ Wt,
                                             int rowlen, int koff, int tid){
    #pragma unroll
    for (int i = 0; i < 4; i++){
        int idx = tid + 512*i;
        int seg = idx & 7, n = idx >> 3;
        cpasync16(bs_u32 + (uint32_t)(n*144 + seg*16),
                  Wt + n*rowlen + koff + seg*8);
    }
}
// full attn A: Af[r][0..255] = cos(Xs[r][..] + theta)
__device__ __forceinline__ void stageA_attn_full(__half* __restrict__ Af,
        const __half* __restrict__ Xs, const float* __restrict__ theta, int tid){
    #pragma unroll
    for (int i = 0; i < 16; i++){
        int idx = tid + 512*i;
        int kk4 = (idx & 63)*4, r = idx >> 6;
        uint2 xr = *(const uint2*)&Xs[r*XSTR + kk4];
        float2 x01 = __half22float2(*(const __half2*)&xr.x);
        float2 x23 = __half22float2(*(const __half2*)&xr.y);
        __half2 h01 = __floats2half2_rn(__cosf(x01.x + __ldg(&theta[(kk4+0)&63])),
                                        __cosf(x01.y + __ldg(&theta[(kk4+1)&63])));
        __half2 h23 = __floats2half2_rn(__cosf(x23.x + __ldg(&theta[(kk4+2)&63])),
                                        __cosf(x23.y + __ldg(&theta[(kk4+3)&63])));
        uint2 pk; pk.x = *(const uint32_t*)&h01; pk.y = *(const uint32_t*)&h23;
        *(uint2*)&Af[r*XSTR + kk4] = pk;
    }
}
// full h K-half: Af[r][f] = relu(q[r]·W1[:,kh*256+f] + b1)  f in [0,256)
__device__ __forceinline__ void stageA_ffn_half(__half* __restrict__ Af,
        const float* __restrict__ qs, const float* __restrict__ W1,
        const float* __restrict__ b1, int kh, int tid){
    int fc = (tid & 127)*2, rg = tid >> 7;   // 4 groups of 32 rows, column pair fc
    float w0[8], w1[8];
    #pragma unroll
    for (int n = 0; n < 8; n++){
        w0[n] = __ldg(&W1[n*FFND + kh*256 + fc]);
        w1[n] = __ldg(&W1[n*FFND + kh*256 + fc + 1]);
    }
    float b0 = __ldg(&b1[kh*256 + fc]), b1v = __ldg(&b1[kh*256 + fc + 1]);
    #pragma unroll 8
    for (int rr = 0; rr < 32; rr++){
        int r = rg*32 + rr;
        float a0 = b0, a1 = b1v;
        #pragma unroll
        for (int n = 0; n < 8; n++){
            float qv = qs[r*9 + n];
            a0 += qv * w0[n]; a1 += qv * w1[n];
        }
        __half2 h = __floats2half2_rn(fmaxf(a0, 0.f), fmaxf(a1, 0.f));
        *(uint32_t*)&Af[r*XSTR + fc] = *(const uint32_t*)&h;
    }
}

// ---------------- register epilogue: Xs = LN(Xs + D + bias) ----------------
__device__ __forceinline__ void epilogue(__half* __restrict__ Xs, float* __restrict__ S,
        float acc[2][8][4], int wm, int wn, int gid, int tig,
        const float* __restrict__ bias, const float* __restrict__ lng,
        const float* __restrict__ lnb){
    #pragma unroll
    for (int tm = 0; tm < 2; tm++){
        int rl = wm*32 + tm*16 + gid;
        #pragma unroll
        for (int tn = 0; tn < 8; tn++){
            int col = wn*64 + tn*8 + 2*tig;
            float bx = __ldg(&bias[col]), by = __ldg(&bias[col+1]);
            float2 x0 = __half22float2(*(const __half2*)&Xs[rl*XSTR + col]);
            float2 x1 = __half22float2(*(const __half2*)&Xs[(rl+8)*XSTR + col]);
            acc[tm][tn][0] += bx + x0.x; acc[tm][tn][1] += by + x0.y;
            acc[tm][tn][2] += bx + x1.x; acc[tm][tn][3] += by + x1.y;
        }
    }
    float s[2][2], q[2][2];
    #pragma unroll
    for (int tm = 0; tm < 2; tm++){
        s[tm][0] = s[tm][1] = q[tm][0] = q[tm][1] = 0.f;
        #pragma unroll
        for (int tn = 0; tn < 8; tn++){
            s[tm][0] += acc[tm][tn][0] + acc[tm][tn][1];
            q[tm][0] += acc[tm][tn][0]*acc[tm][tn][0] + acc[tm][tn][1]*acc[tm][tn][1];
            s[tm][1] += acc[tm][tn][2] + acc[tm][tn][3];
            q[tm][1] += acc[tm][tn][2]*acc[tm][tn][2] + acc[tm][tn][3]*acc[tm][tn][3];
        }
    }
    #pragma unroll
    for (int off = 1; off <= 2; off <<= 1)
        #pragma unroll
        for (int tm = 0; tm < 2; tm++)
            #pragma unroll
            for (int h = 0; h < 2; h++){
                s[tm][h] += __shfl_xor_sync(0xffffffffu, s[tm][h], off);
                q[tm][h] += __shfl_xor_sync(0xffffffffu, q[tm][h], off);
            }
    if (tig == 0){
        #pragma unroll
        for (int tm = 0; tm < 2; tm++){
            int rl = wm*32 + tm*16 + gid;
            S[rl*8 + wn*2]        = s[tm][0];
            S[rl*8 + wn*2 + 1]    = q[tm][0];
            S[(rl+8)*8 + wn*2]    = s[tm][1];
            S[(rl+8)*8 + wn*2 +1] = q[tm][1];
        }
    }
    __syncthreads();
    #pragma unroll
    for (int tm = 0; tm < 2; tm++){
        int rl = wm*32 + tm*16 + gid;
        #pragma unroll
        for (int h = 0; h < 2; h++){
            int r = rl + 8*h;
            float Ss = S[r*8+0] + S[r*8+2] + S[r*8+4] + S[r*8+6];
            float Qq = S[r*8+1] + S[r*8+3] + S[r*8+5] + S[r*8+7];
            float m  = Ss * (1.f/256.f);
            float var = fmaxf(Qq * (1.f/256.f) - m*m, 0.f);
            float rs = rsqrtf(var + 1e-5f);
            #pragma unroll
            for (int tn = 0; tn < 8; tn++){
                int col = wn*64 + tn*8 + 2*tig;
                float z0 = acc[tm][tn][2*h], z1 = acc[tm][tn][2*h+1];
                *(__half2*)&Xs[r*XSTR + col] =
                    __floats2half2_rn((z0-m)*rs*__ldg(&lng[col]) + __ldg(&lnb[col]),
                                      (z1-m)*rs*__ldg(&lng[col+1]) + __ldg(&lnb[col+1]));
            }
        }
    }
}

// ---------------- fused kernel ----------------
__global__ __launch_bounds__(512, 1) void k_fused(
    const int* __restrict__ tokens, const float* __restrict__ embed,
    const float* __restrict__ attn_theta, const float* __restrict__ combine_b,
    const float* __restrict__ ffn_theta,  const float* __restrict__ lin1_w,
    const float* __restrict__ lin1_b,     const float* __restrict__ lin2_b,
    const float* __restrict__ ln1g, const float* __restrict__ ln1b,
    const float* __restrict__ ln2g, const float* __restrict__ ln2b)
{
    extern __shared__ char sm[];
    __half* Xs  = (__half*)sm;
    __half* Af  = (__half*)(sm + OFF_AF);
    __half* Bs  = (__half*)(sm + OFF_BS);
    float*  qs  = (float*)(sm + OFF_QS);
    float*  S   = (float*)(sm + OFF_AF);   // alias (post-GEMM only)
    uint32_t af_u32 = smem_u32(Af);
    uint32_t bs_u32 = smem_u32(Bs);

    int tid = threadIdx.x, lane = tid & 31, wid = tid >> 5;
    int gid = lane >> 2, tig = lane & 3;
    int wm = wid & 3, wn = wid >> 2;    // 4m x 4n, warp tile 32 x 64
    int row0 = blockIdx.x * ROWS;

    // ---- embed + positional encoding (fp16 Xs) ----
    #pragma unroll 4
    for (int i = 0; i < 16; i++){
        int idx = tid + 512*i;
        int r = idx >> 6, c4 = (idx & 63) * 4;
        int tok = __ldg(&tokens[row0 + r]);
        float4 v = *(const float4*)&embed[tok*EMB + c4];
        float pos = (float)((row0 + r) & (SEQ-1));
        float s0,c0,s1,c1;
        sincosf(pos * g_freq[(c4>>1)+0], &s0, &c0);
        sincosf(pos * g_freq[(c4>>1)+1], &s1, &c1);
        __half2 lo = __floats2half2_rn(v.x + s0, v.y + c0);
        __half2 hi = __floats2half2_rn(v.z + s1, v.w + c1);
        uint2 pk; pk.x = *(const uint32_t*)&lo; pk.y = *(const uint32_t*)&hi;
        *(uint2*)&Xs[r*XSTR + c4] = pk;
    }
    __syncthreads();

    #pragma unroll 1
    for (int l = 0; l < 2; l++){
        // ========== attention: full A staged, 4 pure-mma K-chunks ==========
        {
            const float*  theta = attn_theta + l*64;
            const __half* Wt    = g_wt_attn + l*65536;
            float acc[2][8][4];
            float* ap = &acc[0][0][0];
            #pragma unroll
            for (int j = 0; j < 64; j++) ap[j] = 0.f;

            stageB_async(bs_u32, Wt, 256, 0, tid);
            cpcommit();
            stageA_attn_full(Af, Xs, theta, tid);
            cpwait0(); __syncthreads();

            #pragma unroll 1
            for (int c = 0; c < 4; c++){
                int cur = c & 1, nxt = cur ^ 1;
                if (c + 1 < 4){
                    stageB_async(bs_u32 + nxt*BBUF, Wt, 256, (c+1)*64, tid);
                    cpcommit();
                }
                mma_chunk(af_u32 + (uint32_t)(c*128), bs_u32 + cur*BBUF, wm, wn, lane, acc);
                if (c + 1 < 4) cpwait0();
                __syncthreads();
            }
            epilogue(Xs, S, acc, wm, wn, gid, tig,
                     combine_b + l*256, ln1g + l*256, ln1b + l*256);
            __syncthreads();
        }
        // ========== ffn: h staged per K-half, 2 x 4 pure-mma chunks ==========
        {
            const float*  fth = ffn_theta + l*8;
            const float*  W1  = lin1_w + l*8*FFND;
            const float*  b1  = lin1_b + l*FFND;
            const __half* Wt2 = g_wt_ffn + l*256*FFND;
            float acc[2][8][4];
            float* ap = &acc[0][0][0];
            #pragma unroll
            for (int j = 0; j < 64; j++) ap[j] = 0.f;

            for (int idx = tid; idx < ROWS*8; idx += 512){
                int r = idx >> 3, n = idx & 7;
                qs[r*9 + n] = __cosf(__half2float(Xs[r*XSTR + n])) * __cosf(__ldg(&fth[n]));
            }
            __syncthreads();

            #pragma unroll 1
            for (int kh = 0; kh < 2; kh++){
                stageB_async(bs_u32, Wt2, 512, kh*256, tid);
                cpcommit();
                stageA_ffn_half(Af, qs, W1, b1, kh, tid);
                cpwait0(); __syncthreads();

                #pragma unroll 1
                for (int c = 0; c < 4; c++){
                    int cur = c & 1, nxt = cur ^ 1;
                    if (c + 1 < 4){
                        stageB_async(bs_u32 + nxt*BBUF, Wt2, 512, kh*256 + (c+1)*64, tid);
                        cpcommit();
                    }
                    mma_chunk(af_u32 + (uint32_t)(c*128), bs_u32 + cur*BBUF, wm, wn, lane, acc);
                    if (c + 1 < 4) cpwait0();
                    __syncthreads();
                }
            }
            epilogue(Xs, S, acc, wm, wn, gid, tig,
                     lin2_b + l*256, ln2g + l*256, ln2b + l*256);
            __syncthreads();
        }
    }

    // ---- partial pool: column sums over this CTA's 128 rows ----
    {
        int col = tid & 255, half = tid >> 8;
        float s = 0.f;
        #pragma unroll 8
        for (int r = half*64; r < half*64 + 64; r++) s += __half2float(Xs[r*XSTR + col]);
        float* P = (float*)(sm + OFF_AF);
        P[half*256 + col] = s;
        __syncthreads();
        if (tid < 256)
            g_pool[blockIdx.x*256 + tid] = P[tid] + P[256 + tid];
    }
}

// ---------------- classifier ----------------
__global__ void k_cls2(const float* __restrict__ cw, const float* __restrict__ cb,
                       float* __restrict__ out){
    int b = blockIdx.x, tid = threadIdx.x;
    float s = 0.f;
    #pragma unroll
    for (int seg = 0; seg < 16; seg++) s += g_pool[(b*16+seg)*256 + tid];
    float p = s * (1.f/(float)SEQ);
    float l0 = p * cw[tid*2 + 0];
    float l1 = p * cw[tid*2 + 1];
    #pragma unroll
    for (int off=16; off; off>>=1){
        l0 += __shfl_xor_sync(0xffffffffu, l0, off);
        l1 += __shfl_xor_sync(0xffffffffu, l1, off);
    }
    __shared__ float r0[8], r1[8];
    int warp = tid >> 5, lane = tid & 31;
    if (lane == 0){ r0[warp] = l0; r1[warp] = l1; }
    __syncthreads();
    if (tid == 0){
        float a = cb[0], c = cb[1];
        #pragma unroll
        for (int w = 0; w < 8; w++){ a += r0[w]; c += r1[w]; }
        out[b*2 + 0] = a; out[b*2 + 1] = c;
    }
}

// ---------------- launch ----------------
extern "C" void kernel_launch(void* const* d_in, const int* in_sizes, int n_in,
                              void* d_out, int out_size){
    const int*   tokens     = (const int*)  d_in[0];
    const float* embed      = (const float*)d_in[1];
    const float* attn_theta = (const float*)d_in[2];
    const float* combine_w  = (const float*)d_in[3];
    const float* combine_b  = (const float*)d_in[4];
    const float* ffn_theta  = (const float*)d_in[5];
    const float* lin1_w     = (const float*)d_in[6];
    const float* lin1_b     = (const float*)d_in[7];
    const float* lin2_w     = (const float*)d_in[8];
    const float* lin2_b     = (const float*)d_in[9];
    const float* ln1_g      = (const float*)d_in[10];
    const float* ln1_b      = (const float*)d_in[11];
    const float* ln2_g      = (const float*)d_in[12];
    const float* ln2_b      = (const float*)d_in[13];
    const float* cls_w      = (const float*)d_in[14];
    const float* cls_b      = (const float*)d_in[15];
    float* out = (float*)d_out;

    static int inited = 0;
    if (!inited){
        cudaFuncSetAttribute(k_fused, cudaFuncAttributeMaxDynamicSharedMemorySize, SM_TOT);
        inited = 1;
    }

    k_freq<<<1, 128>>>();
    {
        dim3 ga(256, 2); k_tr_attn<<<ga, 256>>>(combine_w);
        dim3 gf(512, 2); k_tr_ffn<<<gf, 256>>>(lin2_w);
    }
    k_fused<<<NROWS/ROWS, 512, SM_TOT>>>(tokens, embed,
        attn_theta, combine_b, ffn_theta, lin1_w, lin1_b, lin2_b,
        ln1_g, ln1_b, ln2_g, ln2_b);
    k_cls2<<<NBATCH, 256>>>(cls_w, cls_b, out);
}